// round 4
// baseline (speedup 1.0000x reference)
#include <cuda_runtime.h>
#include <cuda_fp16.h>
#include <cstdint>

#define DIM   192
#define NTOK  64
#define NH    6
#define HD    32
#define QKV_N 576
#define SCALE 0.17677669529663689f   // 1/sqrt(32)

#define XS 200   // fp16 row stride (halves) for 192-col tiles (bank-safe for ldmatrix)
#define AS 72    // fp16 row stride for 64-col attn tile

#define SMEM_BYTES ((4 * NTOK * XS + NTOK * AS) * 2 + 256 * 4)   // 112640

// ---- persistent fp16 weights + gathered relative-position bias ----
__device__ __half g_qkv_w[QKV_N * DIM];
__device__ __half g_proj_w[DIM * DIM];
__device__ float  g_rpb[NH * NTOK * NTOK];

__global__ void prep_kernel(const float* __restrict__ qkv_w,
                            const float* __restrict__ proj_w,
                            const float* __restrict__ bias_table,
                            const int*   __restrict__ rel_idx) {
    int i = blockIdx.x * blockDim.x + threadIdx.x;
    if (i < QKV_N * DIM) g_qkv_w[i] = __float2half(qkv_w[i]);
    if (i < DIM * DIM)   g_proj_w[i] = __float2half(proj_w[i]);
    if (i < NTOK * NTOK) {
        int idx = rel_idx[i];
        #pragma unroll
        for (int h = 0; h < NH; h++)
            g_rpb[h * (NTOK * NTOK) + i] = bias_table[idx * NH + h];
    }
}

// ---- PTX helpers ----
__device__ __forceinline__ unsigned sptr(const void* p) {
    return (unsigned)__cvta_generic_to_shared(p);
}
__device__ __forceinline__ void ldm_x4(unsigned addr, unsigned& a0, unsigned& a1,
                                       unsigned& a2, unsigned& a3) {
    asm volatile("ldmatrix.sync.aligned.m8n8.x4.shared.b16 {%0,%1,%2,%3}, [%4];\n"
                 : "=r"(a0), "=r"(a1), "=r"(a2), "=r"(a3) : "r"(addr));
}
__device__ __forceinline__ void ldm_x2(unsigned addr, unsigned& b0, unsigned& b1) {
    asm volatile("ldmatrix.sync.aligned.m8n8.x2.shared.b16 {%0,%1}, [%2];\n"
                 : "=r"(b0), "=r"(b1) : "r"(addr));
}
__device__ __forceinline__ void ldm_x2t(unsigned addr, unsigned& b0, unsigned& b1) {
    asm volatile("ldmatrix.sync.aligned.m8n8.x2.trans.shared.b16 {%0,%1}, [%2];\n"
                 : "=r"(b0), "=r"(b1) : "r"(addr));
}
__device__ __forceinline__ void mma16816(float c[4], unsigned a0, unsigned a1,
                                         unsigned a2, unsigned a3,
                                         unsigned b0, unsigned b1) {
    asm volatile(
        "mma.sync.aligned.m16n8k16.row.col.f32.f16.f16.f32 "
        "{%0,%1,%2,%3}, {%4,%5,%6,%7}, {%8,%9}, {%0,%1,%2,%3};\n"
        : "+f"(c[0]), "+f"(c[1]), "+f"(c[2]), "+f"(c[3])
        : "r"(a0), "r"(a1), "r"(a2), "r"(a3), "r"(b0), "r"(b1));
}

__global__ __launch_bounds__(256, 2)
void winattn_kernel(const float* __restrict__ x,
                    const float* __restrict__ mask,
                    const float* __restrict__ qkv_b,
                    const float* __restrict__ proj_b,
                    float* __restrict__ out) {
    extern __shared__ __align__(16) char smem_raw[];
    __half* sQ = (__half*)smem_raw;
    __half* sK = sQ + NTOK * XS;
    __half* sV = sK + NTOK * XS;
    __half* sY = sV + NTOK * XS;          // aliases sX during stage 0/1
    __half* sA = sY + NTOK * XS;
    float*  sMax = (float*)(sA + NTOK * AS);   // [2][64]
    float*  sSum = sMax + 128;                 // [2][64]

    const int b    = blockIdx.x;
    const int w    = b & 63;
    const int tid  = threadIdx.x;
    const int warp = tid >> 5;
    const int lane = tid & 31;

    const int warpM = warp & 3;            // 16-row tile
    const int warpN = warp >> 2;           // 0..1
    const int r0 = warpM * 16 + (lane >> 2);
    const int cq = (lane & 3) * 2;

    __half* sX = sY;

    // ---------- stage 0: x -> fp16 smem ----------
    {
        const float4* xg = (const float4*)(x + (size_t)b * (NTOK * DIM));
        for (int i = tid; i < NTOK * DIM / 4; i += 256) {
            float4 v = xg[i];
            int e = i * 4;
            int r = e / DIM, c = e % DIM;
            __half2* dst = (__half2*)&sX[r * XS + c];
            dst[0] = __floats2half2_rn(v.x, v.y);
            dst[1] = __floats2half2_rn(v.z, v.w);
        }
    }
    __syncthreads();

    // ---------- stage 1: qkv = x @ W^T + b ----------
    for (int nb = 0; nb < QKV_N; nb += 64) {
        float acc[4][4] = {};
        const int ncol0 = nb + warpN * 32;
        #pragma unroll 4
        for (int kk = 0; kk < DIM; kk += 16) {
            unsigned a0, a1, a2, a3;
            ldm_x4(sptr(&sX[(warpM * 16 + (lane & 15)) * XS + kk + ((lane >> 4) << 3)]),
                   a0, a1, a2, a3);
            #pragma unroll
            for (int nt = 0; nt < 4; nt++) {
                int n = ncol0 + nt * 8 + (lane >> 2);
                const __half* wp = &g_qkv_w[n * DIM + kk + ((lane & 3) << 1)];
                unsigned b0 = *(const unsigned*)wp;
                unsigned b1 = *(const unsigned*)(wp + 8);
                mma16816(acc[nt], a0, a1, a2, a3, b0, b1);
            }
        }
        #pragma unroll
        for (int nt = 0; nt < 4; nt++) {
            int cc = ncol0 + nt * 8 + cq;
            float bb0 = qkv_b[cc], bb1 = qkv_b[cc + 1];
            float v0 = acc[nt][0] + bb0, v1 = acc[nt][1] + bb1;
            float v2 = acc[nt][2] + bb0, v3 = acc[nt][3] + bb1;
            __half* dstbuf; int cl; float sc;
            if (cc < 192)      { dstbuf = sQ; cl = cc;       sc = SCALE; }
            else if (cc < 384) { dstbuf = sK; cl = cc - 192; sc = 1.0f;  }
            else               { dstbuf = sV; cl = cc - 384; sc = 1.0f;  }
            *(__half2*)&dstbuf[r0 * XS + cl]       = __floats2half2_rn(v0 * sc, v1 * sc);
            *(__half2*)&dstbuf[(r0 + 8) * XS + cl] = __floats2half2_rn(v2 * sc, v3 * sc);
        }
    }
    __syncthreads();

    // ---------- stage 2: per-head attention ----------
    const float* maskw = mask + (size_t)w * (NTOK * NTOK);
    #pragma unroll 1
    for (int h = 0; h < NH; h++) {
        // scores: warp computes 16x32 tile of (64x64)
        float sc[4][4] = {};
        #pragma unroll
        for (int kk = 0; kk < HD; kk += 16) {
            unsigned a0, a1, a2, a3;
            ldm_x4(sptr(&sQ[(warpM * 16 + (lane & 15)) * XS + h * HD + kk + ((lane >> 4) << 3)]),
                   a0, a1, a2, a3);
            #pragma unroll
            for (int nt = 0; nt < 4; nt++) {
                unsigned b0, b1;
                ldm_x2(sptr(&sK[(warpN * 32 + nt * 8 + (lane & 7)) * XS + h * HD + kk +
                               (((lane >> 3) & 1) << 3)]),
                       b0, b1);
                mma16816(sc[nt], a0, a1, a2, a3, b0, b1);
            }
        }
        // + relative position bias + shift mask
        const float* rpbh = g_rpb + h * (NTOK * NTOK);
        #pragma unroll
        for (int nt = 0; nt < 4; nt++) {
            int cc = warpN * 32 + nt * 8 + cq;
            float2 rb0 = *(const float2*)&rpbh[r0 * 64 + cc];
            float2 mk0 = *(const float2*)&maskw[r0 * 64 + cc];
            float2 rb1 = *(const float2*)&rpbh[(r0 + 8) * 64 + cc];
            float2 mk1 = *(const float2*)&maskw[(r0 + 8) * 64 + cc];
            sc[nt][0] += rb0.x + mk0.x;  sc[nt][1] += rb0.y + mk0.y;
            sc[nt][2] += rb1.x + mk1.x;  sc[nt][3] += rb1.y + mk1.y;
        }
        // softmax (rows r0, r0+8)
        float m0 = -1e30f, m1 = -1e30f;
        #pragma unroll
        for (int nt = 0; nt < 4; nt++) {
            m0 = fmaxf(m0, fmaxf(sc[nt][0], sc[nt][1]));
            m1 = fmaxf(m1, fmaxf(sc[nt][2], sc[nt][3]));
        }
        m0 = fmaxf(m0, __shfl_xor_sync(0xffffffffu, m0, 1));
        m0 = fmaxf(m0, __shfl_xor_sync(0xffffffffu, m0, 2));
        m1 = fmaxf(m1, __shfl_xor_sync(0xffffffffu, m1, 1));
        m1 = fmaxf(m1, __shfl_xor_sync(0xffffffffu, m1, 2));
        if ((lane & 3) == 0) {
            sMax[warpN * 64 + r0]     = m0;
            sMax[warpN * 64 + r0 + 8] = m1;
        }
        __syncthreads();
        m0 = fmaxf(sMax[r0], sMax[64 + r0]);
        m1 = fmaxf(sMax[r0 + 8], sMax[64 + r0 + 8]);
        float s0 = 0.f, s1 = 0.f;
        #pragma unroll
        for (int nt = 0; nt < 4; nt++) {
            sc[nt][0] = __expf(sc[nt][0] - m0);
            sc[nt][1] = __expf(sc[nt][1] - m0);
            sc[nt][2] = __expf(sc[nt][2] - m1);
            sc[nt][3] = __expf(sc[nt][3] - m1);
            s0 += sc[nt][0] + sc[nt][1];
            s1 += sc[nt][2] + sc[nt][3];
        }
        s0 += __shfl_xor_sync(0xffffffffu, s0, 1);
        s0 += __shfl_xor_sync(0xffffffffu, s0, 2);
        s1 += __shfl_xor_sync(0xffffffffu, s1, 1);
        s1 += __shfl_xor_sync(0xffffffffu, s1, 2);
        if ((lane & 3) == 0) {
            sSum[warpN * 64 + r0]     = s0;
            sSum[warpN * 64 + r0 + 8] = s1;
        }
        __syncthreads();
        float inv0 = 1.0f / (sSum[r0] + sSum[64 + r0]);
        float inv1 = 1.0f / (sSum[r0 + 8] + sSum[64 + r0 + 8]);
        #pragma unroll
        for (int nt = 0; nt < 4; nt++) {
            int cc = warpN * 32 + nt * 8 + cq;
            *(__half2*)&sA[r0 * AS + cc] =
                __floats2half2_rn(sc[nt][0] * inv0, sc[nt][1] * inv0);
            *(__half2*)&sA[(r0 + 8) * AS + cc] =
                __floats2half2_rn(sc[nt][2] * inv1, sc[nt][3] * inv1);
        }
        __syncthreads();

        // attn @ V : warp computes 16x16 tile of (64x32)
        float o[2][4] = {};
        #pragma unroll
        for (int kk = 0; kk < NTOK; kk += 16) {
            unsigned a0, a1, a2, a3;
            ldm_x4(sptr(&sA[(warpM * 16 + (lane & 15)) * AS + kk + ((lane >> 4) << 3)]),
                   a0, a1, a2, a3);
            #pragma unroll
            for (int nt = 0; nt < 2; nt++) {
                unsigned b0, b1;
                ldm_x2t(sptr(&sV[(kk + (lane & 15)) * XS + h * HD + warpN * 16 + nt * 8]),
                        b0, b1);
                mma16816(o[nt], a0, a1, a2, a3, b0, b1);
            }
        }
        #pragma unroll
        for (int nt = 0; nt < 2; nt++) {
            int cc = h * HD + warpN * 16 + nt * 8 + cq;
            *(__half2*)&sY[r0 * XS + cc]       = __floats2half2_rn(o[nt][0], o[nt][1]);
            *(__half2*)&sY[(r0 + 8) * XS + cc] = __floats2half2_rn(o[nt][2], o[nt][3]);
        }
        __syncthreads();
    }

    // ---------- stage 3: out = y @ proj_w^T + proj_b ----------
    float* og = out + (size_t)b * (NTOK * DIM);
    for (int nb = 0; nb < DIM; nb += 64) {
        float acc[4][4] = {};
        const int ncol0 = nb + warpN * 32;
        #pragma unroll 4
        for (int kk = 0; kk < DIM; kk += 16) {
            unsigned a0, a1, a2, a3;
            ldm_x4(sptr(&sY[(warpM * 16 + (lane & 15)) * XS + kk + ((lane >> 4) << 3)]),
                   a0, a1, a2, a3);
            #pragma unroll
            for (int nt = 0; nt < 4; nt++) {
                int n = ncol0 + nt * 8 + (lane >> 2);
                const __half* wp = &g_proj_w[n * DIM + kk + ((lane & 3) << 1)];
                unsigned b0 = *(const unsigned*)wp;
                unsigned b1 = *(const unsigned*)(wp + 8);
                mma16816(acc[nt], a0, a1, a2, a3, b0, b1);
            }
        }
        #pragma unroll
        for (int nt = 0; nt < 4; nt++) {
            int cc = ncol0 + nt * 8 + cq;
            float pb0 = proj_b[cc], pb1 = proj_b[cc + 1];
            *(float2*)&og[r0 * DIM + cc] =
                make_float2(acc[nt][0] + pb0, acc[nt][1] + pb1);
            *(float2*)&og[(r0 + 8) * DIM + cc] =
                make_float2(acc[nt][2] + pb0, acc[nt][3] + pb1);
        }
    }
}

extern "C" void kernel_launch(void* const* d_in, const int* in_sizes, int n_in,
                              void* d_out, int out_size) {
    const float* x          = (const float*)d_in[0];
    const float* mask       = (const float*)d_in[1];
    const float* qkv_w      = (const float*)d_in[2];
    const float* qkv_b      = (const float*)d_in[3];
    const float* proj_w     = (const float*)d_in[4];
    const float* proj_b     = (const float*)d_in[5];
    const float* bias_table = (const float*)d_in[6];
    const int*   rel_idx    = (const int*)d_in[7];
    float* out = (float*)d_out;

    prep_kernel<<<(QKV_N * DIM + 255) / 256, 256>>>(qkv_w, proj_w, bias_table, rel_idx);

    cudaFuncSetAttribute(winattn_kernel,
                         cudaFuncAttributeMaxDynamicSharedMemorySize, SMEM_BYTES);
    winattn_kernel<<<8192, 256, SMEM_BYTES>>>(x, mask, qkv_b, proj_b, out);
}

// round 7
// speedup vs baseline: 5.2549x; 5.2549x over previous
#include <cuda_runtime.h>
#include <cuda_fp16.h>
#include <cstdint>

#define DIM   192
#define NTOK  64
#define NH    6
#define HD    32
#define QKV_N 576
#define SCALE 0.17677669529663689f   // 1/sqrt(32)

#define XS 200   // fp16 row stride (halves): 400B/row -> 4-bank step, ldmatrix conflict-free

#define SMEM_BYTES (4 * NTOK * XS * 2)   // sX, sQ(/sY), sK, sV = 102400 B

// ---- persistent pre-packed operands ----
// qkv weights as MMA B fragments: [72 nblk][6 kpair][32 lane] -> uint4 {b0,b1 of kk, b0,b1 of kk+1}
__device__ uint4 g_qkv_wf[72 * 6 * 32];
// proj weights: [24 nblk][6 kpair][32 lane]
__device__ uint4 g_proj_wf[24 * 6 * 32];
// combined rpb+mask, fp16, fragment layout: [w][h][m(16-row grp)][nt][lane] -> uint2 {h2(r0,c:c+1), h2(r0+8,c:c+1)}
__device__ uint2 g_bias[64 * NH * 4 * 8 * 32];

#define QKV_FRAGS  (72 * 6 * 32)          // 13824
#define PROJ_FRAGS (24 * 6 * 32)          // 4608
#define BIAS_FRAGS (64 * NH * 4 * 8 * 32) // 393216
#define PREP_TOTAL (QKV_FRAGS + PROJ_FRAGS + BIAS_FRAGS)

__device__ __forceinline__ unsigned packh2(float a, float b) {
    __half2 h = __floats2half2_rn(a, b);
    return *(unsigned*)&h;
}

__global__ void prep_kernel(const float* __restrict__ qkv_w,
                            const float* __restrict__ proj_w,
                            const float* __restrict__ bias_table,
                            const int*   __restrict__ rel_idx,
                            const float* __restrict__ mask) {
    int i = blockIdx.x * blockDim.x + threadIdx.x;
    if (i < QKV_FRAGS) {
        int lane = i & 31, kp = (i >> 5) % 6, nblk = (i >> 5) / 6;
        int n = nblk * 8 + (lane >> 2);
        const float* wp = qkv_w + n * DIM + kp * 32 + (lane & 3) * 2;
        uint4 r;
        r.x = packh2(wp[0],  wp[1]);
        r.y = packh2(wp[8],  wp[9]);
        r.z = packh2(wp[16], wp[17]);
        r.w = packh2(wp[24], wp[25]);
        g_qkv_wf[i] = r;
        return;
    }
    int j = i - QKV_FRAGS;
    if (j < PROJ_FRAGS) {
        int lane = j & 31, kp = (j >> 5) % 6, nblk = (j >> 5) / 6;
        int n = nblk * 8 + (lane >> 2);
        const float* wp = proj_w + n * DIM + kp * 32 + (lane & 3) * 2;
        uint4 r;
        r.x = packh2(wp[0],  wp[1]);
        r.y = packh2(wp[8],  wp[9]);
        r.z = packh2(wp[16], wp[17]);
        r.w = packh2(wp[24], wp[25]);
        g_proj_wf[j] = r;
        return;
    }
    int t = j - PROJ_FRAGS;
    if (t < BIAS_FRAGS) {
        int lane = t & 31;
        int nt   = (t >> 5) & 7;
        int m    = (t >> 8) & 3;
        int rest = t >> 10;
        int h = rest % NH, w = rest / NH;
        int r0 = m * 16 + (lane >> 2);
        int c  = nt * 8 + (lane & 3) * 2;
        const float* mw = mask + (size_t)w * (NTOK * NTOK);
        float v00 = bias_table[rel_idx[r0 * 64 + c] * NH + h]           + mw[r0 * 64 + c];
        float v01 = bias_table[rel_idx[r0 * 64 + c + 1] * NH + h]       + mw[r0 * 64 + c + 1];
        float v10 = bias_table[rel_idx[(r0 + 8) * 64 + c] * NH + h]     + mw[(r0 + 8) * 64 + c];
        float v11 = bias_table[rel_idx[(r0 + 8) * 64 + c + 1] * NH + h] + mw[(r0 + 8) * 64 + c + 1];
        uint2 r;
        r.x = packh2(v00, v01);
        r.y = packh2(v10, v11);
        g_bias[t] = r;
    }
}

// ---- PTX helpers ----
__device__ __forceinline__ unsigned sptr(const void* p) {
    return (unsigned)__cvta_generic_to_shared(p);
}
__device__ __forceinline__ void ldm_x4(unsigned addr, unsigned& a0, unsigned& a1,
                                       unsigned& a2, unsigned& a3) {
    asm volatile("ldmatrix.sync.aligned.m8n8.x4.shared.b16 {%0,%1,%2,%3}, [%4];\n"
                 : "=r"(a0), "=r"(a1), "=r"(a2), "=r"(a3) : "r"(addr));
}
__device__ __forceinline__ void ldm_x2(unsigned addr, unsigned& b0, unsigned& b1) {
    asm volatile("ldmatrix.sync.aligned.m8n8.x2.shared.b16 {%0,%1}, [%2];\n"
                 : "=r"(b0), "=r"(b1) : "r"(addr));
}
__device__ __forceinline__ void ldm_x2t(unsigned addr, unsigned& b0, unsigned& b1) {
    asm volatile("ldmatrix.sync.aligned.m8n8.x2.trans.shared.b16 {%0,%1}, [%2];\n"
                 : "=r"(b0), "=r"(b1) : "r"(addr));
}
__device__ __forceinline__ void mma16816(float c[4], unsigned a0, unsigned a1,
                                         unsigned a2, unsigned a3,
                                         unsigned b0, unsigned b1) {
    asm volatile(
        "mma.sync.aligned.m16n8k16.row.col.f32.f16.f16.f32 "
        "{%0,%1,%2,%3}, {%4,%5,%6,%7}, {%8,%9}, {%0,%1,%2,%3};\n"
        : "+f"(c[0]), "+f"(c[1]), "+f"(c[2]), "+f"(c[3])
        : "r"(a0), "r"(a1), "r"(a2), "r"(a3), "r"(b0), "r"(b1));
}

__global__ __launch_bounds__(256, 2)
void winattn_kernel(const float* __restrict__ x,
                    const float* __restrict__ qkv_b,
                    const float* __restrict__ proj_b,
                    float* __restrict__ out) {
    extern __shared__ __align__(16) char smem_raw[];
    __half* sX = (__half*)smem_raw;
    __half* sQ = sX + NTOK * XS;   // Y overwrites Q head-by-head in stage 2
    __half* sK = sQ + NTOK * XS;
    __half* sV = sK + NTOK * XS;

    const int b    = blockIdx.x;
    const int w    = b & 63;
    const int tid  = threadIdx.x;
    const int warp = tid >> 5;
    const int lane = tid & 31;

    const int warpM = warp & 3;       // 16-row group (used by all stages)
    const int warpN = warp >> 2;      // 0..1 (GEMM col half)
    const int hpair = warp >> 2;      // attention head parity
    const int r0 = warpM * 16 + (lane >> 2);
    const int cq = (lane & 3) * 2;

    // ---------- stage 0: x -> fp16 smem ----------
    {
        const float4* xg = (const float4*)(x + (size_t)b * (NTOK * DIM));
        for (int i = tid; i < NTOK * DIM / 4; i += 256) {
            float4 v = xg[i];
            int e = i * 4;
            int r = e / DIM, c = e % DIM;
            __half2* dst = (__half2*)&sX[r * XS + c];
            dst[0] = __floats2half2_rn(v.x, v.y);
            dst[1] = __floats2half2_rn(v.z, v.w);
        }
    }
    __syncthreads();

    // ---------- stage 1: qkv = x @ W^T + b (A fragments hoisted) ----------
    {
        unsigned Afr[12][4];
        unsigned abase = sptr(&sX[(warpM * 16 + (lane & 15)) * XS + ((lane >> 4) << 3)]);
        #pragma unroll
        for (int kb = 0; kb < 12; kb++)
            ldm_x4(abase + kb * 32, Afr[kb][0], Afr[kb][1], Afr[kb][2], Afr[kb][3]);

        #pragma unroll 1
        for (int nb = 0; nb < 9; nb++) {
            float acc[4][4] = {};
            const int nblk0 = nb * 8 + warpN * 4;
            #pragma unroll
            for (int kp = 0; kp < 6; kp++) {
                #pragma unroll
                for (int nt = 0; nt < 4; nt++) {
                    uint4 bb = g_qkv_wf[((nblk0 + nt) * 6 + kp) * 32 + lane];
                    mma16816(acc[nt], Afr[2*kp][0], Afr[2*kp][1], Afr[2*kp][2], Afr[2*kp][3],
                             bb.x, bb.y);
                    mma16816(acc[nt], Afr[2*kp+1][0], Afr[2*kp+1][1], Afr[2*kp+1][2], Afr[2*kp+1][3],
                             bb.z, bb.w);
                }
            }
            #pragma unroll
            for (int nt = 0; nt < 4; nt++) {
                int cc = nb * 64 + warpN * 32 + nt * 8 + cq;
                float bb0 = qkv_b[cc], bb1 = qkv_b[cc + 1];
                float v0 = acc[nt][0] + bb0, v1 = acc[nt][1] + bb1;
                float v2 = acc[nt][2] + bb0, v3 = acc[nt][3] + bb1;
                __half* dstbuf; int cl; float sc;
                if (cc < 192)      { dstbuf = sQ; cl = cc;       sc = SCALE; }
                else if (cc < 384) { dstbuf = sK; cl = cc - 192; sc = 1.0f;  }
                else               { dstbuf = sV; cl = cc - 384; sc = 1.0f;  }
                *(__half2*)&dstbuf[r0 * XS + cl]       = __floats2half2_rn(v0 * sc, v1 * sc);
                *(__half2*)&dstbuf[(r0 + 8) * XS + cl] = __floats2half2_rn(v2 * sc, v3 * sc);
            }
        }
    }
    __syncthreads();

    // ---------- stage 2: attention. warp = 16 rows x 64 cols; heads {hpair, 2+hpair, 4+hpair}.
    // Softmax fully intra-warp; score C-fragments feed P@V as A-fragments in registers.
    // Y (head cols) overwrites Q (same head cols): hpair 0 touches even heads only,
    // hpair 1 odd heads only -> no cross-warp hazard, zero barriers inside the loop.
    #pragma unroll 1
    for (int hi = 0; hi < 3; hi++) {
        const int h = hi * 2 + hpair;
        float sc[8][4] = {};
        #pragma unroll
        for (int kk2 = 0; kk2 < 2; kk2++) {
            unsigned a0, a1, a2, a3;
            ldm_x4(sptr(&sQ[(warpM * 16 + (lane & 15)) * XS + h * HD + kk2 * 16 + ((lane >> 4) << 3)]),
                   a0, a1, a2, a3);
            #pragma unroll
            for (int nt = 0; nt < 8; nt++) {
                unsigned b0, b1;
                ldm_x2(sptr(&sK[(nt * 8 + (lane & 7)) * XS + h * HD + kk2 * 16 +
                               (((lane >> 3) & 1) << 3)]),
                       b0, b1);
                mma16816(sc[nt], a0, a1, a2, a3, b0, b1);
            }
        }
        // + combined rpb+mask (fp16 fragment table, coalesced)
        {
            const uint2* bp = &g_bias[(((w * NH + h) * 4 + warpM) * 8) * 32 + lane];
            #pragma unroll
            for (int nt = 0; nt < 8; nt++) {
                uint2 bv = bp[nt * 32];
                __half2 lo = *(__half2*)&bv.x, hi2 = *(__half2*)&bv.y;
                sc[nt][0] += __low2float(lo);  sc[nt][1] += __high2float(lo);
                sc[nt][2] += __low2float(hi2); sc[nt][3] += __high2float(hi2);
            }
        }
        // intra-warp softmax (rows r0, r0+8)
        float m0 = -1e30f, m1 = -1e30f;
        #pragma unroll
        for (int nt = 0; nt < 8; nt++) {
            m0 = fmaxf(m0, fmaxf(sc[nt][0], sc[nt][1]));
            m1 = fmaxf(m1, fmaxf(sc[nt][2], sc[nt][3]));
        }
        m0 = fmaxf(m0, __shfl_xor_sync(0xffffffffu, m0, 1));
        m0 = fmaxf(m0, __shfl_xor_sync(0xffffffffu, m0, 2));
        m1 = fmaxf(m1, __shfl_xor_sync(0xffffffffu, m1, 1));
        m1 = fmaxf(m1, __shfl_xor_sync(0xffffffffu, m1, 2));
        float s0 = 0.f, s1 = 0.f;
        #pragma unroll
        for (int nt = 0; nt < 8; nt++) {
            sc[nt][0] = __expf(sc[nt][0] - m0);
            sc[nt][1] = __expf(sc[nt][1] - m0);
            sc[nt][2] = __expf(sc[nt][2] - m1);
            sc[nt][3] = __expf(sc[nt][3] - m1);
            s0 += sc[nt][0] + sc[nt][1];
            s1 += sc[nt][2] + sc[nt][3];
        }
        s0 += __shfl_xor_sync(0xffffffffu, s0, 1);
        s0 += __shfl_xor_sync(0xffffffffu, s0, 2);
        s1 += __shfl_xor_sync(0xffffffffu, s1, 1);
        s1 += __shfl_xor_sync(0xffffffffu, s1, 2);
        const float inv0 = 1.0f / s0;
        const float inv1 = 1.0f / s1;

        // P @ V : P fragments built in-register from score C-fragments
        float o[4][4] = {};
        #pragma unroll
        for (int j = 0; j < 4; j++) {          // token blocks of 16
            unsigned a0 = packh2(sc[2*j][0]   * inv0, sc[2*j][1]   * inv0);
            unsigned a1 = packh2(sc[2*j][2]   * inv1, sc[2*j][3]   * inv1);
            unsigned a2 = packh2(sc[2*j+1][0] * inv0, sc[2*j+1][1] * inv0);
            unsigned a3 = packh2(sc[2*j+1][2] * inv1, sc[2*j+1][3] * inv1);
            #pragma unroll
            for (int nt = 0; nt < 4; nt++) {
                unsigned b0, b1;
                ldm_x2t(sptr(&sV[(j * 16 + (lane & 15)) * XS + h * HD + nt * 8]), b0, b1);
                mma16816(o[nt], a0, a1, a2, a3, b0, b1);
            }
        }
        // write Y over Q's head columns (warp-local rows, head-parity cols)
        #pragma unroll
        for (int nt = 0; nt < 4; nt++) {
            int cc = h * HD + nt * 8 + cq;
            *(__half2*)&sQ[r0 * XS + cc]       = __floats2half2_rn(o[nt][0], o[nt][1]);
            *(__half2*)&sQ[(r0 + 8) * XS + cc] = __floats2half2_rn(o[nt][2], o[nt][3]);
        }
    }
    __syncthreads();

    // ---------- stage 3: out = y @ proj_w^T + proj_b (A fragments hoisted) ----------
    {
        unsigned Yfr[12][4];
        unsigned ybase = sptr(&sQ[(warpM * 16 + (lane & 15)) * XS + ((lane >> 4) << 3)]);
        #pragma unroll
        for (int kb = 0; kb < 12; kb++)
            ldm_x4(ybase + kb * 32, Yfr[kb][0], Yfr[kb][1], Yfr[kb][2], Yfr[kb][3]);

        float* og = out + (size_t)b * (NTOK * DIM);
        #pragma unroll 1
        for (int nb = 0; nb < 3; nb++) {
            float acc[4][4] = {};
            const int nblk0 = nb * 8 + warpN * 4;
            #pragma unroll
            for (int kp = 0; kp < 6; kp++) {
                #pragma unroll
                for (int nt = 0; nt < 4; nt++) {
                    uint4 bb = g_proj_wf[((nblk0 + nt) * 6 + kp) * 32 + lane];
                    mma16816(acc[nt], Yfr[2*kp][0], Yfr[2*kp][1], Yfr[2*kp][2], Yfr[2*kp][3],
                             bb.x, bb.y);
                    mma16816(acc[nt], Yfr[2*kp+1][0], Yfr[2*kp+1][1], Yfr[2*kp+1][2], Yfr[2*kp+1][3],
                             bb.z, bb.w);
                }
            }
            #pragma unroll
            for (int nt = 0; nt < 4; nt++) {
                int cc = nb * 64 + warpN * 32 + nt * 8 + cq;
                float pb0 = proj_b[cc], pb1 = proj_b[cc + 1];
                *(float2*)&og[r0 * DIM + cc] =
                    make_float2(acc[nt][0] + pb0, acc[nt][1] + pb1);
                *(float2*)&og[(r0 + 8) * DIM + cc] =
                    make_float2(acc[nt][2] + pb0, acc[nt][3] + pb1);
            }
        }
    }
}

extern "C" void kernel_launch(void* const* d_in, const int* in_sizes, int n_in,
                              void* d_out, int out_size) {
    const float* x          = (const float*)d_in[0];
    const float* mask       = (const float*)d_in[1];
    const float* qkv_w      = (const float*)d_in[2];
    const float* qkv_b      = (const float*)d_in[3];
    const float* proj_w     = (const float*)d_in[4];
    const float* proj_b     = (const float*)d_in[5];
    const float* bias_table = (const float*)d_in[6];
    const int*   rel_idx    = (const int*)d_in[7];
    float* out = (float*)d_out;

    prep_kernel<<<(PREP_TOTAL + 255) / 256, 256>>>(qkv_w, proj_w, bias_table, rel_idx, mask);

    cudaFuncSetAttribute(winattn_kernel,
                         cudaFuncAttributeMaxDynamicSharedMemorySize, SMEM_BYTES);
    winattn_kernel<<<8192, 256, SMEM_BYTES>>>(x, qkv_b, proj_b, out);
}